// round 5
// baseline (speedup 1.0000x reference)
#include <cuda_runtime.h>

// out[j]     = dot(X[r1(j)], p), r1(j) = inds1[2j]*28 + inds1[2j+1], j in [0,100)
// out[100+j] = dot(Y[r2(j)], p)
// 200 dots x 4 segments = 800 blocks x 256 threads. Each thread front-batches
// 16 independent LDG.128 (8 row + 8 p) to keep DRAM loads outstanding for the
// bulk of the warp lifetime. Per-dot ticket: 4th arriving segment block sums
// the 4 partials in fixed order (deterministic) and writes out[dot].

#define Q       32768
#define QV      (Q / 4)         // 8192 float4 per row
#define NSEG    4
#define SEGF4   (QV / NSEG)     // 2048 float4 per segment
#define NT      256
#define W_DIM   28
#define NDOTS   200
#define NBLK    (NDOTS * NSEG)  // 800

__device__ float        g_partial[NDOTS * NSEG];
__device__ unsigned int g_cnt[NDOTS];   // zero-init; reset by finisher each launch

__device__ __forceinline__ float dot4(float4 a, float4 b) {
    return a.x * b.x + a.y * b.y + a.z * b.z + a.w * b.w;
}

__global__ __launch_bounds__(NT)
void dot_kernel(const float* __restrict__ X,
                const float* __restrict__ Y,
                const float* __restrict__ p,
                const int*   __restrict__ inds1,
                const int*   __restrict__ inds2,
                float* __restrict__ out)
{
    const int b   = blockIdx.x;           // 0..799
    const int j   = b >> 2;               // dot 0..199
    const int seg = b & (NSEG - 1);       // 0..3

    const bool second = (j >= 100);
    const int jj = second ? (j - 100) : j;
    const int* __restrict__ inds = second ? inds2 : inds1;
    const float* __restrict__ M  = second ? Y : X;

    const int r = inds[2 * jj] * W_DIM + inds[2 * jj + 1];

    const float4* __restrict__ row = reinterpret_cast<const float4*>(M + (size_t)r * Q);
    const float4* __restrict__ pv  = reinterpret_cast<const float4*>(p);

    const int i0 = seg * SEGF4 + threadIdx.x;

    // 16 independent LDG.128, all issued before any consumption.
    float4 a0 = row[i0];
    float4 a1 = row[i0 +     NT];
    float4 a2 = row[i0 + 2 * NT];
    float4 a3 = row[i0 + 3 * NT];
    float4 a4 = row[i0 + 4 * NT];
    float4 a5 = row[i0 + 5 * NT];
    float4 a6 = row[i0 + 6 * NT];
    float4 a7 = row[i0 + 7 * NT];
    float4 b0 = pv [i0];
    float4 b1 = pv [i0 +     NT];
    float4 b2 = pv [i0 + 2 * NT];
    float4 b3 = pv [i0 + 3 * NT];
    float4 b4 = pv [i0 + 4 * NT];
    float4 b5 = pv [i0 + 5 * NT];
    float4 b6 = pv [i0 + 6 * NT];
    float4 b7 = pv [i0 + 7 * NT];

    float sum = dot4(a0, b0);
    sum += dot4(a1, b1);
    sum += dot4(a2, b2);
    sum += dot4(a3, b3);
    sum += dot4(a4, b4);
    sum += dot4(a5, b5);
    sum += dot4(a6, b6);
    sum += dot4(a7, b7);

    // warp reduce
    #pragma unroll
    for (int off = 16; off > 0; off >>= 1)
        sum += __shfl_xor_sync(0xFFFFFFFFu, sum, off);

    __shared__ float warp_sums[NT / 32];
    const int lane = threadIdx.x & 31;
    const int wid  = threadIdx.x >> 5;
    if (lane == 0) warp_sums[wid] = sum;
    __syncthreads();

    if (threadIdx.x == 0) {
        float s = warp_sums[0];
        #pragma unroll
        for (int w = 1; w < NT / 32; w++) s += warp_sums[w];

        g_partial[j * NSEG + seg] = s;
        __threadfence();                                // publish partial
        unsigned int t = atomicAdd(&g_cnt[j], 1u);
        if (t == NSEG - 1) {
            __threadfence();                            // acquire others' partials
            const volatile float* gp = g_partial + j * NSEG;
            float acc = gp[0];                          // fixed order -> deterministic
            #pragma unroll
            for (int k = 1; k < NSEG; k++) acc += gp[k];
            out[j] = acc;
            g_cnt[j] = 0;                               // reset for next replay
        }
    }
}

extern "C" void kernel_launch(void* const* d_in, const int* in_sizes, int n_in,
                              void* d_out, int out_size)
{
    const float* X   = (const float*)d_in[0];
    const float* Y   = (const float*)d_in[1];
    const float* p   = (const float*)d_in[2];
    const int* inds1 = (const int*)d_in[3];
    const int* inds2 = (const int*)d_in[4];
    float* out       = (float*)d_out;

    dot_kernel<<<NBLK, NT>>>(X, Y, p, inds1, inds2, out);
}